// round 7
// baseline (speedup 1.0000x reference)
#include <cuda_runtime.h>
#include <cuda_bf16.h>
#include <cuda_fp16.h>
#include <cstdint>

#define N_NODES 100000
#define N_EDGES 1600000
#define D 64
#define TILE_M 128
#define NBLK_SCAN ((N_NODES + 1023) / 1024)   // 98
#define NODE_BLOCKS ((N_NODES + TILE_M - 1) / TILE_M)  // 782

#define A_STRIDE 136   // halves per A row (128 + 8 pad)
#define B_STRIDE 136   // halves per B row (128 + 8 pad)

// SMEM layout (bytes, dynamic)
#define SM_BIAS 0
#define SM_FC   256
#define SM_OUT  512
#define SM_AHI  1024
#define SM_ALO  (SM_AHI + 128 * A_STRIDE * 2)   // +34816
#define SM_BHI  (SM_ALO + 128 * A_STRIDE * 2)
#define SM_BLO  (SM_BHI + 64 * B_STRIDE * 2)    // +17408
#define SMEM_TOTAL (SM_BLO + 64 * B_STRIDE * 2) // 105472 bytes

// Scratch (allocation-free: __device__ globals)
__device__ float  g_h1[(size_t)N_NODES * D];
__device__ __half g_x16[(size_t)N_NODES * D];
__device__ __half g_h16[(size_t)N_NODES * D];
__device__ int   g_count[N_NODES];
__device__ int   g_off[N_NODES + 1];
__device__ int   g_cursor[N_NODES];
__device__ int   g_nbr[N_EDGES];
__device__ float g_inv[N_NODES];
__device__ int   g_blocksums[NBLK_SCAN];

// ---------------------------------------------------------------------------
// helpers
// ---------------------------------------------------------------------------
__device__ __forceinline__ void mma_bf16(float* d, const uint32_t* a,
                                         uint32_t b0, uint32_t b1) {
    asm volatile(
        "mma.sync.aligned.m16n8k16.row.col.f32.bf16.bf16.f32 "
        "{%0,%1,%2,%3}, {%4,%5,%6,%7}, {%8,%9}, {%0,%1,%2,%3};"
        : "+f"(d[0]), "+f"(d[1]), "+f"(d[2]), "+f"(d[3])
        : "r"(a[0]), "r"(a[1]), "r"(a[2]), "r"(a[3]), "r"(b0), "r"(b1));
}

__device__ __forceinline__ void bf_split(float v, unsigned short& h, unsigned short& l) {
    __nv_bfloat16 bh = __float2bfloat16(v);
    __nv_bfloat16 bl = __float2bfloat16(v - __bfloat162float(bh));
    h = __bfloat16_as_ushort(bh);
    l = __bfloat16_as_ushort(bl);
}
__device__ __forceinline__ uint32_t pack2(unsigned short a, unsigned short b) {
    return (uint32_t)a | ((uint32_t)b << 16);
}
__device__ __forceinline__ uint32_t h2u(__half2 h) {
    return *reinterpret_cast<uint32_t*>(&h);
}

// ---------------------------------------------------------------------------
// CSR construction (by destination)
// ---------------------------------------------------------------------------
__global__ void zero_count_kernel() {
    int i = blockIdx.x * blockDim.x + threadIdx.x;
    if (i < N_NODES) g_count[i] = 0;
}

// histogram + x -> fp16 conversion (both ranges are exactly 1.6M)
__global__ void hist_convert_kernel(const int* __restrict__ dst,
                                    const float* __restrict__ x) {
    int e = blockIdx.x * blockDim.x + threadIdx.x;
    if (e < N_EDGES) atomicAdd(&g_count[dst[e]], 1);
    if (e < N_NODES * D / 4) {
        float4 v = ((const float4*)x)[e];
        uint2 u;
        u.x = h2u(__floats2half2_rn(v.x, v.y));
        u.y = h2u(__floats2half2_rn(v.z, v.w));
        ((uint2*)g_x16)[e] = u;
    }
}

__global__ void __launch_bounds__(1024) scan_block_kernel() {
    __shared__ int sh[1024];
    int gi = blockIdx.x * 1024 + threadIdx.x;
    int v = (gi < N_NODES) ? g_count[gi] : 0;
    sh[threadIdx.x] = v;
    __syncthreads();
#pragma unroll
    for (int off = 1; off < 1024; off <<= 1) {
        int t = (threadIdx.x >= off) ? sh[threadIdx.x - off] : 0;
        __syncthreads();
        sh[threadIdx.x] += t;
        __syncthreads();
    }
    int incl = sh[threadIdx.x];
    if (gi < N_NODES) g_off[gi] = incl - v;
    if (threadIdx.x == 1023) g_blocksums[blockIdx.x] = incl;
}

// finish: every block redundantly scans the 98 block sums in shared, then
// applies the offset, builds cursor/inv. (replaces scan_top + scan_finish)
__global__ void __launch_bounds__(256) scan_finish_kernel() {
    __shared__ int stop[128];
    int tid = threadIdx.x;
    if (tid < 128) {
        int v = (tid < NBLK_SCAN) ? g_blocksums[tid] : 0;
        stop[tid] = v;
    }
    __syncthreads();
#pragma unroll
    for (int off = 1; off < 128; off <<= 1) {
        int t = 0;
        if (tid < 128 && tid >= off) t = stop[tid - off];
        __syncthreads();
        if (tid < 128) stop[tid] += t;
        __syncthreads();
    }
    // stop now inclusive; need exclusive: handled by reading [i-1]
    int gi = blockIdx.x * 256 + tid;
    if (gi < N_NODES) {
        int blk = gi >> 10;
        int base = (blk == 0) ? 0 : stop[blk - 1];
        int o = g_off[gi] + base;
        g_off[gi] = o;
        g_cursor[gi] = o;
        int c = g_count[gi];
        g_inv[gi] = c > 0 ? 1.0f / (float)c : 0.f;
    }
    if (gi == 0) g_off[N_NODES] = N_EDGES;
}

__global__ void fill_kernel(const int* __restrict__ src,
                            const int* __restrict__ dst) {
    int e = blockIdx.x * blockDim.x + threadIdx.x;
    if (e < N_EDGES) {
        int p = atomicAdd(&g_cursor[dst[e]], 1);
        g_nbr[p] = src[e];
    }
}

// ---------------------------------------------------------------------------
// Fused tile kernel: fp16 gather -> bf16 hi/lo staging -> mma.sync -> epilogue
//   A = [mean_agg | feat]  (128 x 128 halves), B = Wcat^T (64 x 128)
//   Y = relu(A @ B^T + bl)
// FINAL=false: Y -> g_h1 (fp32) + g_h16 (fp16); FINAL=true: out = Y@Wfc + bfc
// Block = 512 threads = 16 warps; warp w: m-band (w>>1)*16, n-half (w&1)*32.
// ---------------------------------------------------------------------------
template <bool FINAL>
__global__ void __launch_bounds__(512, 2) fused_tile_kernel(
    const float* __restrict__ xin,
    const float* __restrict__ Wl,
    const float* __restrict__ Wr,
    const float* __restrict__ bl,
    const float* __restrict__ Wfc,
    const float* __restrict__ bfc,
    float* __restrict__ outp) {
    extern __shared__ char smem[];
    float* sBias = (float*)(smem + SM_BIAS);
    float* sFc = (float*)(smem + SM_FC);
    float* sOut = (float*)(smem + SM_OUT);

    const int tid = threadIdx.x;
    const int wid = tid >> 5;
    const int lane = tid & 31;
    const int nbase = blockIdx.x * TILE_M;
    const float* feat = FINAL ? g_h1 : xin;
    const __half* gsrc = FINAL ? g_h16 : g_x16;

    if (tid < D) {
        sBias[tid] = bl[tid];
        if (FINAL) sFc[tid] = Wfc[tid];
    }
    if (FINAL && tid < TILE_M) sOut[tid] = 0.f;

    // ---- Stage weights (transposed, hi/lo): B[n][k] = Wcat[k][n] ----
#pragma unroll
    for (int it = 0; it < 8; it++) {
        int idx = tid + 512 * it;          // 4096 (n, k-pair) tasks
        int n = idx >> 6;
        int k0 = (idx & 63) * 2;
        float w0, w1;
        if (k0 < 64) { w0 = Wl[k0 * 64 + n];        w1 = Wl[(k0 + 1) * 64 + n]; }
        else         { w0 = Wr[(k0 - 64) * 64 + n]; w1 = Wr[(k0 - 63) * 64 + n]; }
        unsigned short h0, l0, h1, l1;
        bf_split(w0, h0, l0);
        bf_split(w1, h1, l1);
        *(uint32_t*)(smem + SM_BHI + ((size_t)n * B_STRIDE + k0) * 2) = pack2(h0, h1);
        *(uint32_t*)(smem + SM_BLO + ((size_t)n * B_STRIDE + k0) * 2) = pack2(l0, l1);
    }

    // ---- Stage X half (cols 64..127 of A) from fp32 feat ----
#pragma unroll
    for (int r = 0; r < 8; r++) {
        int m = wid + 16 * r;
        int n = nbase + m;
        uint32_t ph = 0, pl = 0;
        if (n < N_NODES) {
            float2 v = ((const float2*)(feat + (size_t)n * D))[lane];
            unsigned short h0, l0, h1, l1;
            bf_split(v.x, h0, l0);
            bf_split(v.y, h1, l1);
            ph = pack2(h0, h1);
            pl = pack2(l0, l1);
        }
        size_t off = ((size_t)m * A_STRIDE + 64 + lane * 2) * 2;
        *(uint32_t*)(smem + SM_AHI + off) = ph;
        *(uint32_t*)(smem + SM_ALO + off) = pl;
    }

    // ---- Gather (cols 0..63 of A): fp16 rows, fp32 accumulate ----
    {
        const int sub = lane >> 3;   // neighbor slot 0..3
        const int c = lane & 7;      // column octet (8 halves = 16B)
        for (int i = 0; i < 8; i++) {
            int m = wid + 16 * i;
            int n = nbase + m;
            float acc[8];
#pragma unroll
            for (int q = 0; q < 8; q++) acc[q] = 0.f;
            if (n < N_NODES) {
                int jb = g_off[n], je = g_off[n + 1];
                int j = jb + sub;
                for (; j + 4 < je; j += 8) {
                    int s0 = g_nbr[j];
                    int s1 = g_nbr[j + 4];
                    uint4 u0 = ((const uint4*)(gsrc + (size_t)s0 * D))[c];
                    uint4 u1 = ((const uint4*)(gsrc + (size_t)s1 * D))[c];
                    const __half2* p0 = (const __half2*)&u0;
                    const __half2* p1 = (const __half2*)&u1;
#pragma unroll
                    for (int q = 0; q < 4; q++) {
                        float2 f0 = __half22float2(p0[q]);
                        float2 f1 = __half22float2(p1[q]);
                        acc[2 * q]     += f0.x + f1.x;
                        acc[2 * q + 1] += f0.y + f1.y;
                    }
                }
                if (j < je) {
                    int s0 = g_nbr[j];
                    uint4 u0 = ((const uint4*)(gsrc + (size_t)s0 * D))[c];
                    const __half2* p0 = (const __half2*)&u0;
#pragma unroll
                    for (int q = 0; q < 4; q++) {
                        float2 f0 = __half22float2(p0[q]);
                        acc[2 * q]     += f0.x;
                        acc[2 * q + 1] += f0.y;
                    }
                }
            }
#pragma unroll
            for (int q = 0; q < 8; q++) {
                acc[q] += __shfl_xor_sync(0xFFFFFFFFu, acc[q], 16);
                acc[q] += __shfl_xor_sync(0xFFFFFFFFu, acc[q], 8);
            }
            if (sub == 0) {
                float inv = (n < N_NODES) ? g_inv[n] : 0.f;
                uint32_t hi[4], lo[4];
#pragma unroll
                for (int q = 0; q < 4; q++) {
                    unsigned short h0, l0, h1, l1;
                    bf_split(acc[2 * q] * inv, h0, l0);
                    bf_split(acc[2 * q + 1] * inv, h1, l1);
                    hi[q] = pack2(h0, h1);
                    lo[q] = pack2(l0, l1);
                }
                size_t off = ((size_t)m * A_STRIDE + 8 * c) * 2;
                *(uint4*)(smem + SM_AHI + off) = make_uint4(hi[0], hi[1], hi[2], hi[3]);
                *(uint4*)(smem + SM_ALO + off) = make_uint4(lo[0], lo[1], lo[2], lo[3]);
            }
        }
    }

    __syncthreads();

    // ---- Dense: Y = A @ B^T via mma.sync bf16, 3-pass hi/lo ----
    const int g = lane >> 2;
    const int t = lane & 3;
    const int mb = wid >> 1;      // m-band 0..7
    const int nh = wid & 1;       // n-half 0..1

    float acc[4][4];
#pragma unroll
    for (int s = 0; s < 4; s++)
#pragma unroll
        for (int q = 0; q < 4; q++) acc[s][q] = 0.f;

    const char* pAhi = smem + SM_AHI;
    const char* pAlo = smem + SM_ALO;
    const char* pBhi = smem + SM_BHI;
    const char* pBlo = smem + SM_BLO;
    const size_t rowA = (size_t)(mb * 16 + g) * A_STRIDE;
    const size_t rowA8 = rowA + (size_t)8 * A_STRIDE;

#pragma unroll
    for (int ks = 0; ks < 8; ks++) {
        const int k0 = ks * 16;
        uint32_t aHi[4], aLo[4];
        aHi[0] = *(const uint32_t*)(pAhi + (rowA + k0 + 2 * t) * 2);
        aHi[1] = *(const uint32_t*)(pAhi + (rowA8 + k0 + 2 * t) * 2);
        aHi[2] = *(const uint32_t*)(pAhi + (rowA + k0 + 8 + 2 * t) * 2);
        aHi[3] = *(const uint32_t*)(pAhi + (rowA8 + k0 + 8 + 2 * t) * 2);
        aLo[0] = *(const uint32_t*)(pAlo + (rowA + k0 + 2 * t) * 2);
        aLo[1] = *(const uint32_t*)(pAlo + (rowA8 + k0 + 2 * t) * 2);
        aLo[2] = *(const uint32_t*)(pAlo + (rowA + k0 + 8 + 2 * t) * 2);
        aLo[3] = *(const uint32_t*)(pAlo + (rowA8 + k0 + 8 + 2 * t) * 2);
#pragma unroll
        for (int sub = 0; sub < 4; sub++) {
            const int n = nh * 32 + sub * 8 + g;
            const size_t rowB = (size_t)n * B_STRIDE;
            uint32_t bh0 = *(const uint32_t*)(pBhi + (rowB + k0 + 2 * t) * 2);
            uint32_t bh1 = *(const uint32_t*)(pBhi + (rowB + k0 + 8 + 2 * t) * 2);
            uint32_t bl0 = *(const uint32_t*)(pBlo + (rowB + k0 + 2 * t) * 2);
            uint32_t bl1 = *(const uint32_t*)(pBlo + (rowB + k0 + 8 + 2 * t) * 2);
            mma_bf16(acc[sub], aHi, bh0, bh1);
            mma_bf16(acc[sub], aHi, bl0, bl1);
            mma_bf16(acc[sub], aLo, bh0, bh1);
        }
    }

    // ---- Epilogue ----
    const int m0 = mb * 16 + g;
    const int m1 = m0 + 8;
    if (!FINAL) {
#pragma unroll
        for (int sub = 0; sub < 4; sub++) {
            const int col = nh * 32 + sub * 8 + 2 * t;
            const float b0 = sBias[col];
            const float b1 = sBias[col + 1];
            const int n0 = nbase + m0;
            const int n1 = nbase + m1;
            if (n0 < N_NODES) {
                float v0 = fmaxf(acc[sub][0] + b0, 0.f);
                float v1 = fmaxf(acc[sub][1] + b1, 0.f);
                *(float2*)(g_h1 + (size_t)n0 * D + col) = make_float2(v0, v1);
                *(uint32_t*)((char*)g_h16 + ((size_t)n0 * D + col) * 2) =
                    h2u(__floats2half2_rn(v0, v1));
            }
            if (n1 < N_NODES) {
                float v0 = fmaxf(acc[sub][2] + b0, 0.f);
                float v1 = fmaxf(acc[sub][3] + b1, 0.f);
                *(float2*)(g_h1 + (size_t)n1 * D + col) = make_float2(v0, v1);
                *(uint32_t*)((char*)g_h16 + ((size_t)n1 * D + col) * 2) =
                    h2u(__floats2half2_rn(v0, v1));
            }
        }
    } else {
        float p0 = 0.f, p1 = 0.f;
#pragma unroll
        for (int sub = 0; sub < 4; sub++) {
            const int col = nh * 32 + sub * 8 + 2 * t;
            const float b0 = sBias[col];
            const float b1 = sBias[col + 1];
            const float f0 = sFc[col];
            const float f1 = sFc[col + 1];
            p0 += fmaxf(acc[sub][0] + b0, 0.f) * f0 + fmaxf(acc[sub][1] + b1, 0.f) * f1;
            p1 += fmaxf(acc[sub][2] + b0, 0.f) * f0 + fmaxf(acc[sub][3] + b1, 0.f) * f1;
        }
        p0 += __shfl_xor_sync(0xFFFFFFFFu, p0, 1);
        p0 += __shfl_xor_sync(0xFFFFFFFFu, p0, 2);
        p1 += __shfl_xor_sync(0xFFFFFFFFu, p1, 1);
        p1 += __shfl_xor_sync(0xFFFFFFFFu, p1, 2);
        if (t == 0) {
            atomicAdd(sOut + m0, p0);
            atomicAdd(sOut + m1, p1);
        }
        __syncthreads();
        if (tid < TILE_M) {
            int n = nbase + tid;
            if (n < N_NODES) outp[n] = sOut[tid] + bfc[0];
        }
    }
}

// ---------------------------------------------------------------------------
// Launch
// ---------------------------------------------------------------------------
extern "C" void kernel_launch(void* const* d_in, const int* in_sizes, int n_in,
                              void* d_out, int out_size) {
    const float* x = (const float*)d_in[0];
    const int* ei = (const int*)d_in[1];
    const float* Wl1 = (const float*)d_in[2];
    const float* bl1 = (const float*)d_in[3];
    const float* Wr1 = (const float*)d_in[4];
    const float* Wl2 = (const float*)d_in[5];
    const float* bl2 = (const float*)d_in[6];
    const float* Wr2 = (const float*)d_in[7];
    const float* Wfc = (const float*)d_in[8];
    const float* bfc = (const float*)d_in[9];
    float* out = (float*)d_out;

    const int* src = ei;
    const int* dst = ei + N_EDGES;

    const int nblk = (N_NODES + 255) / 256;
    const int eblk = (N_EDGES + 255) / 256;

    cudaFuncSetAttribute(fused_tile_kernel<false>,
                         cudaFuncAttributeMaxDynamicSharedMemorySize, SMEM_TOTAL);
    cudaFuncSetAttribute(fused_tile_kernel<true>,
                         cudaFuncAttributeMaxDynamicSharedMemorySize, SMEM_TOTAL);

    // CSR build + fp16 conversion
    zero_count_kernel<<<nblk, 256>>>();
    hist_convert_kernel<<<eblk, 256>>>(dst, x);
    scan_block_kernel<<<NBLK_SCAN, 1024>>>();
    scan_finish_kernel<<<nblk, 256>>>();
    fill_kernel<<<eblk, 256>>>(src, dst);

    // Layer 1 (fused fp16 gather + mma.sync dense)
    fused_tile_kernel<false><<<NODE_BLOCKS, 512, SMEM_TOTAL>>>(
        x, Wl1, Wr1, bl1, nullptr, nullptr, nullptr);

    // Layer 2 + head
    fused_tile_kernel<true><<<NODE_BLOCKS, 512, SMEM_TOTAL>>>(
        x, Wl2, Wr2, bl2, Wfc, bfc, out);
}

// round 8
// speedup vs baseline: 1.1542x; 1.1542x over previous
#include <cuda_runtime.h>
#include <cuda_bf16.h>
#include <cuda_fp16.h>
#include <cstdint>

#define N_NODES 100000
#define N_EDGES 1600000
#define D 64
#define TILE_M 128
#define NBLK_SCAN ((N_NODES + 1023) / 1024)   // 98
#define NODE_BLOCKS ((N_NODES + TILE_M - 1) / TILE_M)  // 782

#define A_STRIDE 136   // halves per A row (128 + 8 pad)
#define B_STRIDE 136   // halves per B row (128 + 8 pad)

// SMEM layout (bytes, dynamic)
#define SM_BIAS 0
#define SM_FC   256
#define SM_OUT  512
#define SM_A    1024
#define SM_BHI  (SM_A + 128 * A_STRIDE * 2)     // +34816
#define SM_BLO  (SM_BHI + 64 * B_STRIDE * 2)    // +17408
#define SMEM_TOTAL (SM_BLO + 64 * B_STRIDE * 2) // 70656 bytes

// Scratch (allocation-free: __device__ globals)
__device__ __half g_x16[(size_t)N_NODES * D];
__device__ __half g_h16[(size_t)N_NODES * D];
__device__ int   g_count[N_NODES];
__device__ int   g_off[N_NODES + 1];
__device__ int   g_cursor[N_NODES];
__device__ int   g_nbr[N_EDGES];
__device__ float g_inv[N_NODES];
__device__ int   g_blocksums[NBLK_SCAN];

// ---------------------------------------------------------------------------
// helpers
// ---------------------------------------------------------------------------
__device__ __forceinline__ void mma_f16(float* d, const uint32_t* a,
                                        uint32_t b0, uint32_t b1) {
    asm volatile(
        "mma.sync.aligned.m16n8k16.row.col.f32.f16.f16.f32 "
        "{%0,%1,%2,%3}, {%4,%5,%6,%7}, {%8,%9}, {%0,%1,%2,%3};"
        : "+f"(d[0]), "+f"(d[1]), "+f"(d[2]), "+f"(d[3])
        : "r"(a[0]), "r"(a[1]), "r"(a[2]), "r"(a[3]), "r"(b0), "r"(b1));
}

__device__ __forceinline__ void h_split(float v, unsigned short& h, unsigned short& l) {
    __half hh = __float2half_rn(v);
    __half hl = __float2half_rn(v - __half2float(hh));
    h = __half_as_ushort(hh);
    l = __half_as_ushort(hl);
}
__device__ __forceinline__ uint32_t pack2(unsigned short a, unsigned short b) {
    return (uint32_t)a | ((uint32_t)b << 16);
}
__device__ __forceinline__ uint32_t h2u(__half2 h) {
    return *reinterpret_cast<uint32_t*>(&h);
}

// ---------------------------------------------------------------------------
// CSR construction (by destination)
// ---------------------------------------------------------------------------
__global__ void zero_count_kernel() {
    int i = blockIdx.x * blockDim.x + threadIdx.x;
    if (i < N_NODES) g_count[i] = 0;
}

// histogram + x -> fp16 conversion (both ranges are exactly 1.6M)
__global__ void hist_convert_kernel(const int* __restrict__ dst,
                                    const float* __restrict__ x) {
    int e = blockIdx.x * blockDim.x + threadIdx.x;
    if (e < N_EDGES) atomicAdd(&g_count[dst[e]], 1);
    if (e < N_NODES * D / 4) {
        float4 v = ((const float4*)x)[e];
        uint2 u;
        u.x = h2u(__floats2half2_rn(v.x, v.y));
        u.y = h2u(__floats2half2_rn(v.z, v.w));
        ((uint2*)g_x16)[e] = u;
    }
}

__global__ void __launch_bounds__(1024) scan_block_kernel() {
    __shared__ int sh[1024];
    int gi = blockIdx.x * 1024 + threadIdx.x;
    int v = (gi < N_NODES) ? g_count[gi] : 0;
    sh[threadIdx.x] = v;
    __syncthreads();
#pragma unroll
    for (int off = 1; off < 1024; off <<= 1) {
        int t = (threadIdx.x >= off) ? sh[threadIdx.x - off] : 0;
        __syncthreads();
        sh[threadIdx.x] += t;
        __syncthreads();
    }
    int incl = sh[threadIdx.x];
    if (gi < N_NODES) g_off[gi] = incl - v;
    if (threadIdx.x == 1023) g_blocksums[blockIdx.x] = incl;
}

// finish: every block redundantly scans the 98 block sums in shared, then
// applies the offset, builds cursor/inv.
__global__ void __launch_bounds__(256) scan_finish_kernel() {
    __shared__ int stop[128];
    int tid = threadIdx.x;
    if (tid < 128) {
        int v = (tid < NBLK_SCAN) ? g_blocksums[tid] : 0;
        stop[tid] = v;
    }
    __syncthreads();
#pragma unroll
    for (int off = 1; off < 128; off <<= 1) {
        int t = 0;
        if (tid < 128 && tid >= off) t = stop[tid - off];
        __syncthreads();
        if (tid < 128) stop[tid] += t;
        __syncthreads();
    }
    int gi = blockIdx.x * 256 + tid;
    if (gi < N_NODES) {
        int blk = gi >> 10;
        int base = (blk == 0) ? 0 : stop[blk - 1];
        int o = g_off[gi] + base;
        g_off[gi] = o;
        g_cursor[gi] = o;
        int c = g_count[gi];
        g_inv[gi] = c > 0 ? 1.0f / (float)c : 0.f;
    }
    if (gi == 0) g_off[N_NODES] = N_EDGES;
}

__global__ void fill_kernel(const int* __restrict__ src,
                            const int* __restrict__ dst) {
    int e = blockIdx.x * blockDim.x + threadIdx.x;
    if (e < N_EDGES) {
        int p = atomicAdd(&g_cursor[dst[e]], 1);
        g_nbr[p] = src[e];
    }
}

// ---------------------------------------------------------------------------
// Fused tile kernel: fp16 gather -> fp16 A staging -> 2-pass mma.sync f16
//   A = [mean_agg | feat]  (128 x 128 halves, fp16)
//   B = Wcat^T  (64 x 128), fp16 hi/lo (22-bit effective weights)
//   Y = relu(A @ B^T + bl)
// FINAL=false: Y -> g_h16 (fp16); FINAL=true: out = Y @ Wfc + bfc
// Block = 512 threads = 16 warps; warp w: m-band (w>>1)*16, n-half (w&1)*32.
// ---------------------------------------------------------------------------
template <bool FINAL>
__global__ void __launch_bounds__(512, 2) fused_tile_kernel(
    const float* __restrict__ xin,
    const float* __restrict__ Wl,
    const float* __restrict__ Wr,
    const float* __restrict__ bl,
    const float* __restrict__ Wfc,
    const float* __restrict__ bfc,
    float* __restrict__ outp) {
    extern __shared__ char smem[];
    float* sBias = (float*)(smem + SM_BIAS);
    float* sFc = (float*)(smem + SM_FC);
    float* sOut = (float*)(smem + SM_OUT);

    const int tid = threadIdx.x;
    const int wid = tid >> 5;
    const int lane = tid & 31;
    const int nbase = blockIdx.x * TILE_M;
    const __half* gsrc = FINAL ? g_h16 : g_x16;

    if (tid < D) {
        sBias[tid] = bl[tid];
        if (FINAL) sFc[tid] = Wfc[tid];
    }
    if (FINAL && tid < TILE_M) sOut[tid] = 0.f;

    // ---- Stage weights (transposed, fp16 hi/lo): B[n][k] = Wcat[k][n] ----
#pragma unroll
    for (int it = 0; it < 8; it++) {
        int idx = tid + 512 * it;          // 4096 (n, k-pair) tasks
        int n = idx >> 6;
        int k0 = (idx & 63) * 2;
        float w0, w1;
        if (k0 < 64) { w0 = Wl[k0 * 64 + n];        w1 = Wl[(k0 + 1) * 64 + n]; }
        else         { w0 = Wr[(k0 - 64) * 64 + n]; w1 = Wr[(k0 - 63) * 64 + n]; }
        unsigned short h0, l0, h1, l1;
        h_split(w0, h0, l0);
        h_split(w1, h1, l1);
        *(uint32_t*)(smem + SM_BHI + ((size_t)n * B_STRIDE + k0) * 2) = pack2(h0, h1);
        *(uint32_t*)(smem + SM_BLO + ((size_t)n * B_STRIDE + k0) * 2) = pack2(l0, l1);
    }

    // ---- Stage X half (cols 64..127 of A), fp16 ----
#pragma unroll
    for (int r = 0; r < 8; r++) {
        int m = wid + 16 * r;
        int n = nbase + m;
        uint32_t pv = 0;
        if (n < N_NODES) {
            if (FINAL) {
                pv = ((const uint32_t*)(gsrc + (size_t)n * D))[lane];
            } else {
                float2 v = ((const float2*)(xin + (size_t)n * D))[lane];
                pv = h2u(__floats2half2_rn(v.x, v.y));
            }
        }
        *(uint32_t*)(smem + SM_A + ((size_t)m * A_STRIDE + 64 + lane * 2) * 2) = pv;
    }

    // ---- Gather (cols 0..63 of A): fp16 rows, fp32 accumulate, fp16 out ----
    {
        const int sub = lane >> 3;   // neighbor slot 0..3
        const int c = lane & 7;      // column octet (8 halves = 16B)
        for (int i = 0; i < 8; i++) {
            int m = wid + 16 * i;
            int n = nbase + m;
            float acc[8];
#pragma unroll
            for (int q = 0; q < 8; q++) acc[q] = 0.f;
            if (n < N_NODES) {
                int jb = g_off[n], je = g_off[n + 1];
                int j = jb + sub;
                for (; j + 4 < je; j += 8) {
                    int s0 = g_nbr[j];
                    int s1 = g_nbr[j + 4];
                    uint4 u0 = ((const uint4*)(gsrc + (size_t)s0 * D))[c];
                    uint4 u1 = ((const uint4*)(gsrc + (size_t)s1 * D))[c];
                    const __half2* p0 = (const __half2*)&u0;
                    const __half2* p1 = (const __half2*)&u1;
#pragma unroll
                    for (int q = 0; q < 4; q++) {
                        float2 f0 = __half22float2(p0[q]);
                        float2 f1 = __half22float2(p1[q]);
                        acc[2 * q]     += f0.x + f1.x;
                        acc[2 * q + 1] += f0.y + f1.y;
                    }
                }
                if (j < je) {
                    int s0 = g_nbr[j];
                    uint4 u0 = ((const uint4*)(gsrc + (size_t)s0 * D))[c];
                    const __half2* p0 = (const __half2*)&u0;
#pragma unroll
                    for (int q = 0; q < 4; q++) {
                        float2 f0 = __half22float2(p0[q]);
                        acc[2 * q]     += f0.x;
                        acc[2 * q + 1] += f0.y;
                    }
                }
            }
#pragma unroll
            for (int q = 0; q < 8; q++) {
                acc[q] += __shfl_xor_sync(0xFFFFFFFFu, acc[q], 16);
                acc[q] += __shfl_xor_sync(0xFFFFFFFFu, acc[q], 8);
            }
            if (sub == 0) {
                float inv = (n < N_NODES) ? g_inv[n] : 0.f;
                uint32_t pk[4];
#pragma unroll
                for (int q = 0; q < 4; q++) {
                    pk[q] = h2u(__floats2half2_rn(acc[2 * q] * inv,
                                                  acc[2 * q + 1] * inv));
                }
                *(uint4*)(smem + SM_A + ((size_t)m * A_STRIDE + 8 * c) * 2) =
                    make_uint4(pk[0], pk[1], pk[2], pk[3]);
            }
        }
    }

    __syncthreads();

    // ---- Dense: Y = A @ B^T via mma.sync f16, 2-pass (B hi/lo) ----
    const int g = lane >> 2;
    const int t = lane & 3;
    const int mb = wid >> 1;      // m-band 0..7
    const int nh = wid & 1;       // n-half 0..1

    float acc[4][4];
#pragma unroll
    for (int s = 0; s < 4; s++)
#pragma unroll
        for (int q = 0; q < 4; q++) acc[s][q] = 0.f;

    const char* pA = smem + SM_A;
    const char* pBhi = smem + SM_BHI;
    const char* pBlo = smem + SM_BLO;
    const size_t rowA = (size_t)(mb * 16 + g) * A_STRIDE;
    const size_t rowA8 = rowA + (size_t)8 * A_STRIDE;

#pragma unroll
    for (int ks = 0; ks < 8; ks++) {
        const int k0 = ks * 16;
        uint32_t a[4];
        a[0] = *(const uint32_t*)(pA + (rowA + k0 + 2 * t) * 2);
        a[1] = *(const uint32_t*)(pA + (rowA8 + k0 + 2 * t) * 2);
        a[2] = *(const uint32_t*)(pA + (rowA + k0 + 8 + 2 * t) * 2);
        a[3] = *(const uint32_t*)(pA + (rowA8 + k0 + 8 + 2 * t) * 2);
#pragma unroll
        for (int sub = 0; sub < 4; sub++) {
            const int n = nh * 32 + sub * 8 + g;
            const size_t rowB = (size_t)n * B_STRIDE;
            uint32_t bh0 = *(const uint32_t*)(pBhi + (rowB + k0 + 2 * t) * 2);
            uint32_t bh1 = *(const uint32_t*)(pBhi + (rowB + k0 + 8 + 2 * t) * 2);
            uint32_t bl0 = *(const uint32_t*)(pBlo + (rowB + k0 + 2 * t) * 2);
            uint32_t bl1 = *(const uint32_t*)(pBlo + (rowB + k0 + 8 + 2 * t) * 2);
            mma_f16(acc[sub], a, bh0, bh1);
            mma_f16(acc[sub], a, bl0, bl1);
        }
    }

    // ---- Epilogue ----
    const int m0 = mb * 16 + g;
    const int m1 = m0 + 8;
    if (!FINAL) {
#pragma unroll
        for (int sub = 0; sub < 4; sub++) {
            const int col = nh * 32 + sub * 8 + 2 * t;
            const float b0 = sBias[col];
            const float b1 = sBias[col + 1];
            const int n0 = nbase + m0;
            const int n1 = nbase + m1;
            if (n0 < N_NODES) {
                float v0 = fmaxf(acc[sub][0] + b0, 0.f);
                float v1 = fmaxf(acc[sub][1] + b1, 0.f);
                *(uint32_t*)((char*)g_h16 + ((size_t)n0 * D + col) * 2) =
                    h2u(__floats2half2_rn(v0, v1));
            }
            if (n1 < N_NODES) {
                float v0 = fmaxf(acc[sub][2] + b0, 0.f);
                float v1 = fmaxf(acc[sub][3] + b1, 0.f);
                *(uint32_t*)((char*)g_h16 + ((size_t)n1 * D + col) * 2) =
                    h2u(__floats2half2_rn(v0, v1));
            }
        }
    } else {
        float p0 = 0.f, p1 = 0.f;
#pragma unroll
        for (int sub = 0; sub < 4; sub++) {
            const int col = nh * 32 + sub * 8 + 2 * t;
            const float b0 = sBias[col];
            const float b1 = sBias[col + 1];
            const float f0 = sFc[col];
            const float f1 = sFc[col + 1];
            p0 += fmaxf(acc[sub][0] + b0, 0.f) * f0 + fmaxf(acc[sub][1] + b1, 0.f) * f1;
            p1 += fmaxf(acc[sub][2] + b0, 0.f) * f0 + fmaxf(acc[sub][3] + b1, 0.f) * f1;
        }
        p0 += __shfl_xor_sync(0xFFFFFFFFu, p0, 1);
        p0 += __shfl_xor_sync(0xFFFFFFFFu, p0, 2);
        p1 += __shfl_xor_sync(0xFFFFFFFFu, p1, 1);
        p1 += __shfl_xor_sync(0xFFFFFFFFu, p1, 2);
        if (t == 0) {
            atomicAdd(sOut + m0, p0);
            atomicAdd(sOut + m1, p1);
        }
        __syncthreads();
        if (tid < TILE_M) {
            int n = nbase + tid;
            if (n < N_NODES) outp[n] = sOut[tid] + bfc[0];
        }
    }
}

// ---------------------------------------------------------------------------
// Launch
// ---------------------------------------------------------------------------
extern "C" void kernel_launch(void* const* d_in, const int* in_sizes, int n_in,
                              void* d_out, int out_size) {
    const float* x = (const float*)d_in[0];
    const int* ei = (const int*)d_in[1];
    const float* Wl1 = (const float*)d_in[2];
    const float* bl1 = (const float*)d_in[3];
    const float* Wr1 = (const float*)d_in[4];
    const float* Wl2 = (const float*)d_in[5];
    const float* bl2 = (const float*)d_in[6];
    const float* Wr2 = (const float*)d_in[7];
    const float* Wfc = (const float*)d_in[8];
    const float* bfc = (const float*)d_in[9];
    float* out = (float*)d_out;

    const int* src = ei;
    const int* dst = ei + N_EDGES;

    const int nblk = (N_NODES + 255) / 256;
    const int eblk = (N_EDGES + 255) / 256;

    cudaFuncSetAttribute(fused_tile_kernel<false>,
                         cudaFuncAttributeMaxDynamicSharedMemorySize, SMEM_TOTAL);
    cudaFuncSetAttribute(fused_tile_kernel<true>,
                         cudaFuncAttributeMaxDynamicSharedMemorySize, SMEM_TOTAL);

    // CSR build + fp16 conversion
    zero_count_kernel<<<nblk, 256>>>();
    hist_convert_kernel<<<eblk, 256>>>(dst, x);
    scan_block_kernel<<<NBLK_SCAN, 1024>>>();
    scan_finish_kernel<<<nblk, 256>>>();
    fill_kernel<<<eblk, 256>>>(src, dst);

    // Layer 1 (fused fp16 gather + 2-pass mma.sync dense)
    fused_tile_kernel<false><<<NODE_BLOCKS, 512, SMEM_TOTAL>>>(
        x, Wl1, Wr1, bl1, nullptr, nullptr, nullptr);

    // Layer 2 + head
    fused_tile_kernel<true><<<NODE_BLOCKS, 512, SMEM_TOTAL>>>(
        x, Wl2, Wr2, bl2, Wfc, bfc, out);
}

// round 9
// speedup vs baseline: 1.5604x; 1.3518x over previous
#include <cuda_runtime.h>
#include <cuda_fp16.h>
#include <cstdint>

#define N_NODES 100000
#define N_EDGES 1600000
#define D 64
#define TILE_M 128
#define NBLK_SCAN ((N_NODES + 1023) / 1024)   // 98
#define NODE_BLOCKS ((N_NODES + TILE_M - 1) / TILE_M)  // 782

#define A_STRIDE 136   // halves per A row (128 + 8 pad)
#define B_STRIDE 136   // halves per B row (128 + 8 pad)

// SMEM layout (bytes, dynamic)
#define SM_BIAS 0
#define SM_FC   256
#define SM_OUT  512
#define SM_A    1024
#define SM_BHI  (SM_A + 128 * A_STRIDE * 2)     // +34816
#define SM_BLO  (SM_BHI + 64 * B_STRIDE * 2)    // +17408
#define SMEM_TOTAL (SM_BLO + 64 * B_STRIDE * 2) // 70656 bytes

// Scratch (allocation-free: __device__ globals; zero-initialized at load)
__device__ __half g_x16[(size_t)N_NODES * D];
__device__ __half g_h16[(size_t)N_NODES * D];
__device__ int   g_count[N_NODES];     // self-clearing (see scan_finish)
__device__ int   g_off[N_NODES + 1];
__device__ int   g_cursor[N_NODES];
__device__ int   g_nbr[N_EDGES];
__device__ float g_inv[N_NODES];
__device__ int   g_blocksums[NBLK_SCAN];

// ---------------------------------------------------------------------------
// helpers
// ---------------------------------------------------------------------------
__device__ __forceinline__ void mma_f16(float* d, const uint32_t* a,
                                        uint32_t b0, uint32_t b1) {
    asm volatile(
        "mma.sync.aligned.m16n8k16.row.col.f32.f16.f16.f32 "
        "{%0,%1,%2,%3}, {%4,%5,%6,%7}, {%8,%9}, {%0,%1,%2,%3};"
        : "+f"(d[0]), "+f"(d[1]), "+f"(d[2]), "+f"(d[3])
        : "r"(a[0]), "r"(a[1]), "r"(a[2]), "r"(a[3]), "r"(b0), "r"(b1));
}

__device__ __forceinline__ void h_split(float v, unsigned short& h, unsigned short& l) {
    __half hh = __float2half_rn(v);
    __half hl = __float2half_rn(v - __half2float(hh));
    h = __half_as_ushort(hh);
    l = __half_as_ushort(hl);
}
__device__ __forceinline__ uint32_t h2u(__half2 h) {
    return *reinterpret_cast<uint32_t*>(&h);
}

// ---------------------------------------------------------------------------
// CSR construction (by destination)
// ---------------------------------------------------------------------------

// histogram + x -> fp16 conversion (both ranges are exactly 1.6M)
__global__ void hist_convert_kernel(const int* __restrict__ dst,
                                    const float* __restrict__ x) {
    int e = blockIdx.x * blockDim.x + threadIdx.x;
    if (e < N_EDGES) atomicAdd(&g_count[dst[e]], 1);
    if (e < N_NODES * D / 4) {
        float4 v = ((const float4*)x)[e];
        uint2 u;
        u.x = h2u(__floats2half2_rn(v.x, v.y));
        u.y = h2u(__floats2half2_rn(v.z, v.w));
        ((uint2*)g_x16)[e] = u;
    }
}

// per-1024-block exclusive scan via warp shuffles (2 barriers)
__global__ void __launch_bounds__(1024) scan_block_kernel() {
    __shared__ int wsum[32];
    int gi = blockIdx.x * 1024 + threadIdx.x;
    int lane = threadIdx.x & 31;
    int wid = threadIdx.x >> 5;
    int v = (gi < N_NODES) ? g_count[gi] : 0;
    int incl = v;
#pragma unroll
    for (int off = 1; off < 32; off <<= 1) {
        int t = __shfl_up_sync(0xFFFFFFFFu, incl, off);
        if (lane >= off) incl += t;
    }
    if (lane == 31) wsum[wid] = incl;
    __syncthreads();
    if (wid == 0) {
        int wv = wsum[lane];
        int wincl = wv;
#pragma unroll
        for (int off = 1; off < 32; off <<= 1) {
            int t = __shfl_up_sync(0xFFFFFFFFu, wincl, off);
            if (lane >= off) wincl += t;
        }
        wsum[lane] = wincl - wv;   // exclusive warp base
    }
    __syncthreads();
    int excl = incl - v + wsum[wid];
    if (gi < N_NODES) g_off[gi] = excl;
    if (threadIdx.x == 1023) g_blocksums[blockIdx.x] = excl + v;
}

// finish: every block redundantly scans the 98 block sums in shared, applies
// offset, builds cursor/inv, and CLEARS g_count for the next call.
__global__ void __launch_bounds__(256) scan_finish_kernel() {
    __shared__ int stop[128];
    int tid = threadIdx.x;
    if (tid < 128) {
        stop[tid] = (tid < NBLK_SCAN) ? g_blocksums[tid] : 0;
    }
    __syncthreads();
#pragma unroll
    for (int off = 1; off < 128; off <<= 1) {
        int t = 0;
        if (tid < 128 && tid >= off) t = stop[tid - off];
        __syncthreads();
        if (tid < 128) stop[tid] += t;
        __syncthreads();
    }
    int gi = blockIdx.x * 256 + tid;
    if (gi < N_NODES) {
        int blk = gi >> 10;
        int base = (blk == 0) ? 0 : stop[blk - 1];
        int o = g_off[gi] + base;
        g_off[gi] = o;
        g_cursor[gi] = o;
        int c = g_count[gi];
        g_count[gi] = 0;                       // self-clear for next call
        g_inv[gi] = c > 0 ? 1.0f / (float)c : 0.f;
    }
    if (gi == 0) g_off[N_NODES] = N_EDGES;
}

__global__ void fill_kernel(const int* __restrict__ src,
                            const int* __restrict__ dst) {
    int e = blockIdx.x * blockDim.x + threadIdx.x;
    if (e < N_EDGES) {
        int p = atomicAdd(&g_cursor[dst[e]], 1);
        g_nbr[p] = src[e];
    }
}

// ---------------------------------------------------------------------------
// Fused tile kernel: fp16 gather -> fp16 A staging -> 2-pass mma.sync f16
//   A = [mean_agg | feat]  (128 x 128 halves, fp16)
//   B = Wcat^T  (64 x 128), fp16 hi/lo (22-bit effective weights)
//   Y = relu(A @ B^T + bl)
// FINAL=false: Y -> g_h16 (fp16); FINAL=true: out = Y @ Wfc + bfc
// Block = 512 threads = 16 warps; warp w: m-band (w>>1)*16, n-half (w&1)*32.
// ---------------------------------------------------------------------------
template <bool FINAL>
__global__ void __launch_bounds__(512, 2) fused_tile_kernel(
    const float* __restrict__ xin,
    const float* __restrict__ Wl,
    const float* __restrict__ Wr,
    const float* __restrict__ bl,
    const float* __restrict__ Wfc,
    const float* __restrict__ bfc,
    float* __restrict__ outp) {
    extern __shared__ char smem[];
    float* sBias = (float*)(smem + SM_BIAS);
    float* sFc = (float*)(smem + SM_FC);
    float* sOut = (float*)(smem + SM_OUT);

    const int tid = threadIdx.x;
    const int wid = tid >> 5;
    const int lane = tid & 31;
    const int nbase = blockIdx.x * TILE_M;
    const __half* gsrc = FINAL ? g_h16 : g_x16;

    if (tid < D) {
        sBias[tid] = bl[tid];
        if (FINAL) sFc[tid] = Wfc[tid];
    }
    if (FINAL && tid < TILE_M) sOut[tid] = 0.f;

    // ---- Stage weights: coalesced linear read, transpose via SMEM write ----
    // B[n][k] = Wcat[k][n];  Wl covers k 0..63, Wr covers k 64..127.
#pragma unroll
    for (int it = 0; it < 8; it++) {
        int idx = tid + 512 * it;          // linear over Wl [k][n]
        int k = idx >> 6;
        int n = idx & 63;
        unsigned short h, l;
        h_split(Wl[idx], h, l);
        *(unsigned short*)(smem + SM_BHI + ((size_t)n * B_STRIDE + k) * 2) = h;
        *(unsigned short*)(smem + SM_BLO + ((size_t)n * B_STRIDE + k) * 2) = l;
    }
#pragma unroll
    for (int it = 0; it < 8; it++) {
        int idx = tid + 512 * it;          // linear over Wr [k][n]
        int k = (idx >> 6) + 64;
        int n = idx & 63;
        unsigned short h, l;
        h_split(Wr[idx], h, l);
        *(unsigned short*)(smem + SM_BHI + ((size_t)n * B_STRIDE + k) * 2) = h;
        *(unsigned short*)(smem + SM_BLO + ((size_t)n * B_STRIDE + k) * 2) = l;
    }

    // ---- Stage X half (cols 64..127 of A), fp16 ----
#pragma unroll
    for (int r = 0; r < 8; r++) {
        int m = wid + 16 * r;
        int n = nbase + m;
        uint32_t pv = 0;
        if (n < N_NODES) {
            if (FINAL) {
                pv = ((const uint32_t*)(gsrc + (size_t)n * D))[lane];
            } else {
                float2 v = ((const float2*)(xin + (size_t)n * D))[lane];
                pv = h2u(__floats2half2_rn(v.x, v.y));
            }
        }
        *(uint32_t*)(smem + SM_A + ((size_t)m * A_STRIDE + 64 + lane * 2) * 2) = pv;
    }

    // ---- Gather (cols 0..63 of A): half-warp per row, no reductions ----
    // 16 lanes x uint2 (4 halves) = 128B coalesced per neighbor row.
    {
        const int hw = lane >> 4;    // half-warp 0/1
        const int c = lane & 15;     // column quad (4 halves = 8B)
#pragma unroll
        for (int i = 0; i < 4; i++) {
            const int m = (wid * 2 + hw) + 32 * i;
            const int n = nbase + m;
            float a0 = 0.f, a1 = 0.f, a2 = 0.f, a3 = 0.f;
            float b0 = 0.f, b1 = 0.f, b2 = 0.f, b3 = 0.f;
            if (n < N_NODES) {
                const int jb = g_off[n], je = g_off[n + 1];
                int j = jb;
                for (; j + 1 < je; j += 2) {
                    const int s0 = g_nbr[j];
                    const int s1 = g_nbr[j + 1];
                    uint2 u0 = ((const uint2*)(gsrc + (size_t)s0 * D))[c];
                    uint2 u1 = ((const uint2*)(gsrc + (size_t)s1 * D))[c];
                    float2 f0 = __half22float2(*(const __half2*)&u0.x);
                    float2 f1 = __half22float2(*(const __half2*)&u0.y);
                    float2 f2 = __half22float2(*(const __half2*)&u1.x);
                    float2 f3 = __half22float2(*(const __half2*)&u1.y);
                    a0 += f0.x; a1 += f0.y; a2 += f1.x; a3 += f1.y;
                    b0 += f2.x; b1 += f2.y; b2 += f3.x; b3 += f3.y;
                }
                if (j < je) {
                    const int s0 = g_nbr[j];
                    uint2 u0 = ((const uint2*)(gsrc + (size_t)s0 * D))[c];
                    float2 f0 = __half22float2(*(const __half2*)&u0.x);
                    float2 f1 = __half22float2(*(const __half2*)&u0.y);
                    a0 += f0.x; a1 += f0.y; a2 += f1.x; a3 += f1.y;
                }
            }
            a0 += b0; a1 += b1; a2 += b2; a3 += b3;
            const float inv = (n < N_NODES) ? g_inv[n] : 0.f;
            uint2 pk;
            pk.x = h2u(__floats2half2_rn(a0 * inv, a1 * inv));
            pk.y = h2u(__floats2half2_rn(a2 * inv, a3 * inv));
            *(uint2*)(smem + SM_A + ((size_t)m * A_STRIDE + 4 * c) * 2) = pk;
        }
    }

    __syncthreads();

    // ---- Dense: Y = A @ B^T via mma.sync f16, 2-pass (B hi/lo) ----
    const int g = lane >> 2;
    const int t = lane & 3;
    const int mb = wid >> 1;      // m-band 0..7
    const int nh = wid & 1;       // n-half 0..1

    float acc[4][4];
#pragma unroll
    for (int s = 0; s < 4; s++)
#pragma unroll
        for (int q = 0; q < 4; q++) acc[s][q] = 0.f;

    const char* pA = smem + SM_A;
    const char* pBhi = smem + SM_BHI;
    const char* pBlo = smem + SM_BLO;
    const size_t rowA = (size_t)(mb * 16 + g) * A_STRIDE;
    const size_t rowA8 = rowA + (size_t)8 * A_STRIDE;

#pragma unroll
    for (int ks = 0; ks < 8; ks++) {
        const int k0 = ks * 16;
        uint32_t a[4];
        a[0] = *(const uint32_t*)(pA + (rowA + k0 + 2 * t) * 2);
        a[1] = *(const uint32_t*)(pA + (rowA8 + k0 + 2 * t) * 2);
        a[2] = *(const uint32_t*)(pA + (rowA + k0 + 8 + 2 * t) * 2);
        a[3] = *(const uint32_t*)(pA + (rowA8 + k0 + 8 + 2 * t) * 2);
#pragma unroll
        for (int sub = 0; sub < 4; sub++) {
            const int n = nh * 32 + sub * 8 + g;
            const size_t rowB = (size_t)n * B_STRIDE;
            uint32_t bh0 = *(const uint32_t*)(pBhi + (rowB + k0 + 2 * t) * 2);
            uint32_t bh1 = *(const uint32_t*)(pBhi + (rowB + k0 + 8 + 2 * t) * 2);
            uint32_t bl0 = *(const uint32_t*)(pBlo + (rowB + k0 + 2 * t) * 2);
            uint32_t bl1 = *(const uint32_t*)(pBlo + (rowB + k0 + 8 + 2 * t) * 2);
            mma_f16(acc[sub], a, bh0, bh1);
            mma_f16(acc[sub], a, bl0, bl1);
        }
    }

    // ---- Epilogue ----
    const int m0 = mb * 16 + g;
    const int m1 = m0 + 8;
    if (!FINAL) {
#pragma unroll
        for (int sub = 0; sub < 4; sub++) {
            const int col = nh * 32 + sub * 8 + 2 * t;
            const float b0 = sBias[col];
            const float b1 = sBias[col + 1];
            const int n0 = nbase + m0;
            const int n1 = nbase + m1;
            if (n0 < N_NODES) {
                float v0 = fmaxf(acc[sub][0] + b0, 0.f);
                float v1 = fmaxf(acc[sub][1] + b1, 0.f);
                *(uint32_t*)((char*)g_h16 + ((size_t)n0 * D + col) * 2) =
                    h2u(__floats2half2_rn(v0, v1));
            }
            if (n1 < N_NODES) {
                float v0 = fmaxf(acc[sub][2] + b0, 0.f);
                float v1 = fmaxf(acc[sub][3] + b1, 0.f);
                *(uint32_t*)((char*)g_h16 + ((size_t)n1 * D + col) * 2) =
                    h2u(__floats2half2_rn(v0, v1));
            }
        }
    } else {
        float p0 = 0.f, p1 = 0.f;
#pragma unroll
        for (int sub = 0; sub < 4; sub++) {
            const int col = nh * 32 + sub * 8 + 2 * t;
            const float b0 = sBias[col];
            const float b1 = sBias[col + 1];
            const float f0 = sFc[col];
            const float f1 = sFc[col + 1];
            p0 += fmaxf(acc[sub][0] + b0, 0.f) * f0 + fmaxf(acc[sub][1] + b1, 0.f) * f1;
            p1 += fmaxf(acc[sub][2] + b0, 0.f) * f0 + fmaxf(acc[sub][3] + b1, 0.f) * f1;
        }
        p0 += __shfl_xor_sync(0xFFFFFFFFu, p0, 1);
        p0 += __shfl_xor_sync(0xFFFFFFFFu, p0, 2);
        p1 += __shfl_xor_sync(0xFFFFFFFFu, p1, 1);
        p1 += __shfl_xor_sync(0xFFFFFFFFu, p1, 2);
        if (t == 0) {
            atomicAdd(sOut + m0, p0);
            atomicAdd(sOut + m1, p1);
        }
        __syncthreads();
        if (tid < TILE_M) {
            int n = nbase + tid;
            if (n < N_NODES) outp[n] = sOut[tid] + bfc[0];
        }
    }
}

// ---------------------------------------------------------------------------
// Launch
// ---------------------------------------------------------------------------
extern "C" void kernel_launch(void* const* d_in, const int* in_sizes, int n_in,
                              void* d_out, int out_size) {
    const float* x = (const float*)d_in[0];
    const int* ei = (const int*)d_in[1];
    const float* Wl1 = (const float*)d_in[2];
    const float* bl1 = (const float*)d_in[3];
    const float* Wr1 = (const float*)d_in[4];
    const float* Wl2 = (const float*)d_in[5];
    const float* bl2 = (const float*)d_in[6];
    const float* Wr2 = (const float*)d_in[7];
    const float* Wfc = (const float*)d_in[8];
    const float* bfc = (const float*)d_in[9];
    float* out = (float*)d_out;

    const int* src = ei;
    const int* dst = ei + N_EDGES;

    const int nblk = (N_NODES + 255) / 256;
    const int eblk = (N_EDGES + 255) / 256;

    cudaFuncSetAttribute(fused_tile_kernel<false>,
                         cudaFuncAttributeMaxDynamicSharedMemorySize, SMEM_TOTAL);
    cudaFuncSetAttribute(fused_tile_kernel<true>,
                         cudaFuncAttributeMaxDynamicSharedMemorySize, SMEM_TOTAL);

    // CSR build + fp16 conversion (g_count is zero on entry; scan_finish re-zeroes)
    hist_convert_kernel<<<eblk, 256>>>(dst, x);
    scan_block_kernel<<<NBLK_SCAN, 1024>>>();
    scan_finish_kernel<<<nblk, 256>>>();
    fill_kernel<<<eblk, 256>>>(src, dst);

    // Layer 1 (fused fp16 gather + 2-pass mma.sync dense)
    fused_tile_kernel<false><<<NODE_BLOCKS, 512, SMEM_TOTAL>>>(
        x, Wl1, Wr1, bl1, nullptr, nullptr, nullptr);

    // Layer 2 + head
    fused_tile_kernel<true><<<NODE_BLOCKS, 512, SMEM_TOTAL>>>(
        x, Wl2, Wr2, bl2, Wfc, bfc, out);
}

// round 10
// speedup vs baseline: 1.6571x; 1.0620x over previous
#include <cuda_runtime.h>
#include <cuda_fp16.h>
#include <cstdint>

#define N_NODES 100000
#define N_EDGES 1600000
#define D 64
#define TILE_M 128
#define NBLK_SCAN ((N_NODES + 1023) / 1024)   // 98
#define NODE_BLOCKS ((N_NODES + TILE_M - 1) / TILE_M)  // 782

#define A_STRIDE 136   // halves per A row (128 + 8 pad)
#define B_STRIDE 136   // halves per B row (128 + 8 pad)

// SMEM layout (bytes, dynamic)
#define SM_BIAS 0
#define SM_FC   256
#define SM_OUT  512
#define SM_A    1024
#define SM_BHI  (SM_A + 128 * A_STRIDE * 2)     // +34816
#define SM_BLO  (SM_BHI + 64 * B_STRIDE * 2)    // +17408
#define SMEM_TOTAL (SM_BLO + 64 * B_STRIDE * 2) // 70656 bytes

// Scratch (allocation-free: __device__ globals; zero-initialized at load)
__device__ __half g_x16[(size_t)N_NODES * D];
__device__ __half g_h16[(size_t)N_NODES * D];
__device__ __half g_whi[2][64 * 128];   // pre-transposed hi weights [n][k]
__device__ __half g_wlo[2][64 * 128];   // pre-transposed lo weights [n][k]
__device__ int   g_count[N_NODES];      // self-clearing (see scan_finish)
__device__ int   g_off[N_NODES + 1];
__device__ int   g_cursor[N_NODES];
__device__ int   g_nbr[N_EDGES];
__device__ float g_inv[N_NODES];
__device__ int   g_blocksums[NBLK_SCAN];

// ---------------------------------------------------------------------------
// helpers
// ---------------------------------------------------------------------------
__device__ __forceinline__ void mma_f16(float* d, const uint32_t* a,
                                        uint32_t b0, uint32_t b1) {
    asm volatile(
        "mma.sync.aligned.m16n8k16.row.col.f32.f16.f16.f32 "
        "{%0,%1,%2,%3}, {%4,%5,%6,%7}, {%8,%9}, {%0,%1,%2,%3};"
        : "+f"(d[0]), "+f"(d[1]), "+f"(d[2]), "+f"(d[3])
        : "r"(a[0]), "r"(a[1]), "r"(a[2]), "r"(a[3]), "r"(b0), "r"(b1));
}

__device__ __forceinline__ void h_split(float v, __half& h, __half& l) {
    h = __float2half_rn(v);
    l = __float2half_rn(v - __half2float(h));
}
__device__ __forceinline__ uint32_t h2u(__half2 h) {
    return *reinterpret_cast<uint32_t*>(&h);
}

// ---------------------------------------------------------------------------
// CSR construction + one-time conversions
// ---------------------------------------------------------------------------

// histogram + x->fp16 conversion + weight transpose/split (all in one grid)
__global__ void hist_convert_kernel(const int* __restrict__ dst,
                                    const float* __restrict__ x,
                                    const float* __restrict__ Wl1,
                                    const float* __restrict__ Wr1,
                                    const float* __restrict__ Wl2,
                                    const float* __restrict__ Wr2) {
    int e = blockIdx.x * blockDim.x + threadIdx.x;
    if (e < N_EDGES) atomicAdd(&g_count[dst[e]], 1);
    if (e < N_NODES * D / 4) {
        float4 v = ((const float4*)x)[e];
        uint2 u;
        u.x = h2u(__floats2half2_rn(v.x, v.y));
        u.y = h2u(__floats2half2_rn(v.z, v.w));
        ((uint2*)g_x16)[e] = u;
    }
    // weight prep: 2 layers x 8192 elements; linear idx = k*64 + n (coalesced W read)
    if (e < 2 * 8192) {
        int L = e >> 13;
        int idx = e & 8191;
        int k = idx >> 6;
        int n = idx & 63;
        const float* Wl = L ? Wl2 : Wl1;
        const float* Wr = L ? Wr2 : Wr1;
        float w = (k < 64) ? Wl[idx] : Wr[idx - 4096];
        __half h, l;
        h_split(w, h, l);
        g_whi[L][n * 128 + k] = h;
        g_wlo[L][n * 128 + k] = l;
    }
}

// per-1024-block exclusive scan via warp shuffles (2 barriers)
__global__ void __launch_bounds__(1024) scan_block_kernel() {
    __shared__ int wsum[32];
    int gi = blockIdx.x * 1024 + threadIdx.x;
    int lane = threadIdx.x & 31;
    int wid = threadIdx.x >> 5;
    int v = (gi < N_NODES) ? g_count[gi] : 0;
    int incl = v;
#pragma unroll
    for (int off = 1; off < 32; off <<= 1) {
        int t = __shfl_up_sync(0xFFFFFFFFu, incl, off);
        if (lane >= off) incl += t;
    }
    if (lane == 31) wsum[wid] = incl;
    __syncthreads();
    if (wid == 0) {
        int wv = wsum[lane];
        int wincl = wv;
#pragma unroll
        for (int off = 1; off < 32; off <<= 1) {
            int t = __shfl_up_sync(0xFFFFFFFFu, wincl, off);
            if (lane >= off) wincl += t;
        }
        wsum[lane] = wincl - wv;   // exclusive warp base
    }
    __syncthreads();
    int excl = incl - v + wsum[wid];
    if (gi < N_NODES) g_off[gi] = excl;
    if (threadIdx.x == 1023) g_blocksums[blockIdx.x] = excl + v;
}

// finish: every block redundantly scans the 98 block sums in shared, applies
// offset, builds cursor/inv, and CLEARS g_count for the next call.
__global__ void __launch_bounds__(256) scan_finish_kernel() {
    __shared__ int stop[128];
    int tid = threadIdx.x;
    if (tid < 128) {
        stop[tid] = (tid < NBLK_SCAN) ? g_blocksums[tid] : 0;
    }
    __syncthreads();
#pragma unroll
    for (int off = 1; off < 128; off <<= 1) {
        int t = 0;
        if (tid < 128 && tid >= off) t = stop[tid - off];
        __syncthreads();
        if (tid < 128) stop[tid] += t;
        __syncthreads();
    }
    int gi = blockIdx.x * 256 + tid;
    if (gi < N_NODES) {
        int blk = gi >> 10;
        int base = (blk == 0) ? 0 : stop[blk - 1];
        int o = g_off[gi] + base;
        g_off[gi] = o;
        g_cursor[gi] = o;
        int c = g_count[gi];
        g_count[gi] = 0;                       // self-clear for next call
        g_inv[gi] = c > 0 ? 1.0f / (float)c : 0.f;
    }
    if (gi == 0) g_off[N_NODES] = N_EDGES;
}

// 2 edges per thread (int2 loads, 2 independent atomic chains)
__global__ void fill_kernel(const int* __restrict__ src,
                            const int* __restrict__ dst) {
    int i = blockIdx.x * blockDim.x + threadIdx.x;
    if (i < N_EDGES / 2) {
        int2 s = ((const int2*)src)[i];
        int2 d = ((const int2*)dst)[i];
        int p0 = atomicAdd(&g_cursor[d.x], 1);
        int p1 = atomicAdd(&g_cursor[d.y], 1);
        g_nbr[p0] = s.x;
        g_nbr[p1] = s.y;
    }
}

// ---------------------------------------------------------------------------
// Fused tile kernel: fp16 gather -> fp16 A staging -> 2-pass mma.sync f16
//   A = [mean_agg | feat]  (128 x 128 halves, fp16)
//   B = Wcat^T  (64 x 128), fp16 hi/lo (22-bit effective weights), precomputed
//   Y = relu(A @ B^T + bl)
// FINAL=false: Y -> g_h16 (fp16); FINAL=true: out = Y @ Wfc + bfc
// Block = 512 threads = 16 warps; warp w: m-band (w>>1)*16, n-half (w&1)*32.
// ---------------------------------------------------------------------------
template <bool FINAL>
__global__ void __launch_bounds__(512, 2) fused_tile_kernel(
    const __half* __restrict__ Whi,
    const __half* __restrict__ Wlo,
    const float* __restrict__ bl,
    const float* __restrict__ Wfc,
    const float* __restrict__ bfc,
    float* __restrict__ outp) {
    extern __shared__ char smem[];
    float* sBias = (float*)(smem + SM_BIAS);
    float* sFc = (float*)(smem + SM_FC);
    float* sOut = (float*)(smem + SM_OUT);

    const int tid = threadIdx.x;
    const int wid = tid >> 5;
    const int lane = tid & 31;
    const int nbase = blockIdx.x * TILE_M;
    const __half* gsrc = FINAL ? g_h16 : g_x16;

    if (tid < D) {
        sBias[tid] = bl[tid];
        if (FINAL) sFc[tid] = Wfc[tid];
    }
    if (FINAL && tid < TILE_M) sOut[tid] = 0.f;

    // ---- Stage weights: coalesced uint4 loads of precomputed hi/lo tiles ----
    // 1024 uint4 per buffer (64 rows x 16); row n -> SMEM row n (B_STRIDE pad)
#pragma unroll
    for (int it = 0; it < 2; it++) {
        int idx = tid + 512 * it;          // 0..1023
        int n = idx >> 4;
        int q = idx & 15;
        uint4 vh = ((const uint4*)Whi)[idx];
        uint4 vl = ((const uint4*)Wlo)[idx];
        *(uint4*)(smem + SM_BHI + ((size_t)n * B_STRIDE + q * 8) * 2) = vh;
        *(uint4*)(smem + SM_BLO + ((size_t)n * B_STRIDE + q * 8) * 2) = vl;
    }

    // ---- Stage X half (cols 64..127 of A), raw fp16 copy ----
#pragma unroll
    for (int r = 0; r < 8; r++) {
        int m = wid + 16 * r;
        int n = nbase + m;
        uint32_t pv = 0;
        if (n < N_NODES) {
            pv = ((const uint32_t*)(gsrc + (size_t)n * D))[lane];
        }
        *(uint32_t*)(smem + SM_A + ((size_t)m * A_STRIDE + 64 + lane * 2) * 2) = pv;
    }

    // ---- Gather (cols 0..63 of A): half-warp per row, no reductions ----
    // 16 lanes x uint2 (4 halves) = 128B coalesced per neighbor row.
    {
        const int hw = lane >> 4;    // half-warp 0/1
        const int c = lane & 15;     // column quad (4 halves = 8B)
#pragma unroll
        for (int i = 0; i < 4; i++) {
            const int m = (wid * 2 + hw) + 32 * i;
            const int n = nbase + m;
            float a0 = 0.f, a1 = 0.f, a2 = 0.f, a3 = 0.f;
            float b0 = 0.f, b1 = 0.f, b2 = 0.f, b3 = 0.f;
            if (n < N_NODES) {
                const int jb = g_off[n], je = g_off[n + 1];
                int j = jb;
                for (; j + 1 < je; j += 2) {
                    const int s0 = g_nbr[j];
                    const int s1 = g_nbr[j + 1];
                    uint2 u0 = ((const uint2*)(gsrc + (size_t)s0 * D))[c];
                    uint2 u1 = ((const uint2*)(gsrc + (size_t)s1 * D))[c];
                    float2 f0 = __half22float2(*(const __half2*)&u0.x);
                    float2 f1 = __half22float2(*(const __half2*)&u0.y);
                    float2 f2 = __half22float2(*(const __half2*)&u1.x);
                    float2 f3 = __half22float2(*(const __half2*)&u1.y);
                    a0 += f0.x; a1 += f0.y; a2 += f1.x; a3 += f1.y;
                    b0 += f2.x; b1 += f2.y; b2 += f3.x; b3 += f3.y;
                }
                if (j < je) {
                    const int s0 = g_nbr[j];
                    uint2 u0 = ((const uint2*)(gsrc + (size_t)s0 * D))[c];
                    float2 f0 = __half22float2(*(const __half2*)&u0.x);
                    float2 f1 = __half22float2(*(const __half2*)&u0.y);
                    a0 += f0.x; a1 += f0.y; a2 += f1.x; a3 += f1.y;
                }
            }
            a0 += b0; a1 += b1; a2 += b2; a3 += b3;
            const float inv = (n < N_NODES) ? g_inv[n] : 0.f;
            uint2 pk;
            pk.x = h2u(__floats2half2_rn(a0 * inv, a1 * inv));
            pk.y = h2u(__floats2half2_rn(a2 * inv, a3 * inv));
            *(uint2*)(smem + SM_A + ((size_t)m * A_STRIDE + 4 * c) * 2) = pk;
        }
    }

    __syncthreads();

    // ---- Dense: Y = A @ B^T via mma.sync f16, 2-pass (B hi/lo) ----
    const int g = lane >> 2;
    const int t = lane & 3;
    const int mb = wid >> 1;      // m-band 0..7
    const int nh = wid & 1;       // n-half 0..1

    float acc[4][4];
#pragma unroll
    for (int s = 0; s < 4; s++)
#pragma unroll
        for (int q = 0; q < 4; q++) acc[s][q] = 0.f;

    const char* pA = smem + SM_A;
    const char* pBhi = smem + SM_BHI;
    const char* pBlo = smem + SM_BLO;
    const size_t rowA = (size_t)(mb * 16 + g) * A_STRIDE;
    const size_t rowA8 = rowA + (size_t)8 * A_STRIDE;

#pragma unroll
    for (int ks = 0; ks < 8; ks++) {
        const int k0 = ks * 16;
        uint32_t a[4];
        a[0] = *(const uint32_t*)(pA + (rowA + k0 + 2 * t) * 2);
        a[1] = *(const uint32_t*)(pA + (rowA8 + k0 + 2 * t) * 2);
        a[2] = *(const uint32_t*)(pA + (rowA + k0 + 8 + 2 * t) * 2);
        a[3] = *(const uint32_t*)(pA + (rowA8 + k0 + 8 + 2 * t) * 2);
#pragma unroll
        for (int sub = 0; sub < 4; sub++) {
            const int n = nh * 32 + sub * 8 + g;
            const size_t rowB = (size_t)n * B_STRIDE;
            uint32_t bh0 = *(const uint32_t*)(pBhi + (rowB + k0 + 2 * t) * 2);
            uint32_t bh1 = *(const uint32_t*)(pBhi + (rowB + k0 + 8 + 2 * t) * 2);
            uint32_t bl0 = *(const uint32_t*)(pBlo + (rowB + k0 + 2 * t) * 2);
            uint32_t bl1 = *(const uint32_t*)(pBlo + (rowB + k0 + 8 + 2 * t) * 2);
            mma_f16(acc[sub], a, bh0, bh1);
            mma_f16(acc[sub], a, bl0, bl1);
        }
    }

    // ---- Epilogue ----
    const int m0 = mb * 16 + g;
    const int m1 = m0 + 8;
    if (!FINAL) {
#pragma unroll
        for (int sub = 0; sub < 4; sub++) {
            const int col = nh * 32 + sub * 8 + 2 * t;
            const float b0 = sBias[col];
            const float b1 = sBias[col + 1];
            const int n0 = nbase + m0;
            const int n1 = nbase + m1;
            if (n0 < N_NODES) {
                float v0 = fmaxf(acc[sub][0] + b0, 0.f);
                float v1 = fmaxf(acc[sub][1] + b1, 0.f);
                *(uint32_t*)((char*)g_h16 + ((size_t)n0 * D + col) * 2) =
                    h2u(__floats2half2_rn(v0, v1));
            }
            if (n1 < N_NODES) {
                float v0 = fmaxf(acc[sub][2] + b0, 0.f);
                float v1 = fmaxf(acc[sub][3] + b1, 0.f);
                *(uint32_t*)((char*)g_h16 + ((size_t)n1 * D + col) * 2) =
                    h2u(__floats2half2_rn(v0, v1));
            }
        }
    } else {
        float p0 = 0.f, p1 = 0.f;
#pragma unroll
        for (int sub = 0; sub < 4; sub++) {
            const int col = nh * 32 + sub * 8 + 2 * t;
            const float b0 = sBias[col];
            const float b1 = sBias[col + 1];
            const float f0 = sFc[col];
            const float f1 = sFc[col + 1];
            p0 += fmaxf(acc[sub][0] + b0, 0.f) * f0 + fmaxf(acc[sub][1] + b1, 0.f) * f1;
            p1 += fmaxf(acc[sub][2] + b0, 0.f) * f0 + fmaxf(acc[sub][3] + b1, 0.f) * f1;
        }
        p0 += __shfl_xor_sync(0xFFFFFFFFu, p0, 1);
        p0 += __shfl_xor_sync(0xFFFFFFFFu, p0, 2);
        p1 += __shfl_xor_sync(0xFFFFFFFFu, p1, 1);
        p1 += __shfl_xor_sync(0xFFFFFFFFu, p1, 2);
        if (t == 0) {
            atomicAdd(sOut + m0, p0);
            atomicAdd(sOut + m1, p1);
        }
        __syncthreads();
        if (tid < TILE_M) {
            int n = nbase + tid;
            if (n < N_NODES) outp[n] = sOut[tid] + bfc[0];
        }
    }
}

// ---------------------------------------------------------------------------
// Launch
// ---------------------------------------------------------------------------
extern "C" void kernel_launch(void* const* d_in, const int* in_sizes, int n_in,
                              void* d_out, int out_size) {
    const float* x = (const float*)d_in[0];
    const int* ei = (const int*)d_in[1];
    const float* Wl1 = (const float*)d_in[2];
    const float* bl1 = (const float*)d_in[3];
    const float* Wr1 = (const float*)d_in[4];
    const float* Wl2 = (const float*)d_in[5];
    const float* bl2 = (const float*)d_in[6];
    const float* Wr2 = (const float*)d_in[7];
    const float* Wfc = (const float*)d_in[8];
    const float* bfc = (const float*)d_in[9];
    float* out = (float*)d_out;

    const int* src = ei;
    const int* dst = ei + N_EDGES;

    const int nblk = (N_NODES + 255) / 256;
    const int eblk = (N_EDGES + 255) / 256;
    const int fblk = (N_EDGES / 2 + 255) / 256;

    cudaFuncSetAttribute(fused_tile_kernel<false>,
                         cudaFuncAttributeMaxDynamicSharedMemorySize, SMEM_TOTAL);
    cudaFuncSetAttribute(fused_tile_kernel<true>,
                         cudaFuncAttributeMaxDynamicSharedMemorySize, SMEM_TOTAL);

    // device-global weight tile addresses (host-visible symbols)
    __half* whi_dev = nullptr;
    __half* wlo_dev = nullptr;
    cudaGetSymbolAddress((void**)&whi_dev, g_whi);
    cudaGetSymbolAddress((void**)&wlo_dev, g_wlo);

    // CSR build + conversions (g_count is zero on entry; scan_finish re-zeroes)
    hist_convert_kernel<<<eblk, 256>>>(dst, x, Wl1, Wr1, Wl2, Wr2);
    scan_block_kernel<<<NBLK_SCAN, 1024>>>();
    scan_finish_kernel<<<nblk, 256>>>();
    fill_kernel<<<fblk, 256>>>(src, dst);

    // Layer 1 (fused fp16 gather + 2-pass mma.sync dense)
    fused_tile_kernel<false><<<NODE_BLOCKS, 512, SMEM_TOTAL>>>(
        whi_dev, wlo_dev, bl1, nullptr, nullptr, nullptr);

    // Layer 2 + head
    fused_tile_kernel<true><<<NODE_BLOCKS, 512, SMEM_TOTAL>>>(
        whi_dev + 64 * 128, wlo_dev + 64 * 128, bl2, Wfc, bfc, out);
}

// round 11
// speedup vs baseline: 1.9747x; 1.1917x over previous
#include <cuda_runtime.h>
#include <cuda_fp16.h>
#include <cstdint>

#define N_NODES 100000
#define N_EDGES 1600000
#define D 64
#define TILE_M 128
#define PAD 96                                  // adjacency slots per node
#define NODE_BLOCKS ((N_NODES + TILE_M - 1) / TILE_M)  // 782

#define A_STRIDE 136   // halves per A row (128 + 8 pad)
#define B_STRIDE 136   // halves per B row (128 + 8 pad)

// SMEM layout (bytes, dynamic)
#define SM_BIAS 0
#define SM_FC   256
#define SM_OUT  512
#define SM_A    1024
#define SM_BHI  (SM_A + 128 * A_STRIDE * 2)     // +34816
#define SM_BLO  (SM_BHI + 64 * B_STRIDE * 2)    // +17408
#define SMEM_TOTAL (SM_BLO + 64 * B_STRIDE * 2) // 70656 bytes

// Scratch (allocation-free: __device__ globals; zero-initialized at load)
__device__ __half g_x16[(size_t)N_NODES * D];
__device__ __half g_h16[(size_t)N_NODES * D];
__device__ __half g_whi[2][64 * 128];   // pre-transposed hi weights [n][k]
__device__ __half g_wlo[2][64 * 128];   // pre-transposed lo weights [n][k]
__device__ int   g_count[N_NODES];      // zero on entry; layer-2 kernel clears
__device__ int   g_nbr[(size_t)N_NODES * PAD];

// ---------------------------------------------------------------------------
// helpers
// ---------------------------------------------------------------------------
__device__ __forceinline__ void mma_f16(float* d, const uint32_t* a,
                                        uint32_t b0, uint32_t b1) {
    asm volatile(
        "mma.sync.aligned.m16n8k16.row.col.f32.f16.f16.f32 "
        "{%0,%1,%2,%3}, {%4,%5,%6,%7}, {%8,%9}, {%0,%1,%2,%3};"
        : "+f"(d[0]), "+f"(d[1]), "+f"(d[2]), "+f"(d[3])
        : "r"(a[0]), "r"(a[1]), "r"(a[2]), "r"(a[3]), "r"(b0), "r"(b1));
}

__device__ __forceinline__ void h_split(float v, __half& h, __half& l) {
    h = __float2half_rn(v);
    l = __float2half_rn(v - __half2float(h));
}
__device__ __forceinline__ uint32_t h2u(__half2 h) {
    return *reinterpret_cast<uint32_t*>(&h);
}

// ---------------------------------------------------------------------------
// One-pass build: padded adjacency + x->fp16 conversion + weight prep
// Grid: 1.6M threads.
//   i < N_EDGES/2      : 2 edges -> atomic slot claim + padded write
//   i < N_NODES*D/4    : x float4 -> 4 halves
//   i < 2*8192         : weight transpose + hi/lo split
// ---------------------------------------------------------------------------
__global__ void build_kernel(const int* __restrict__ src,
                             const int* __restrict__ dst,
                             const float* __restrict__ x,
                             const float* __restrict__ Wl1,
                             const float* __restrict__ Wr1,
                             const float* __restrict__ Wl2,
                             const float* __restrict__ Wr2) {
    int i = blockIdx.x * blockDim.x + threadIdx.x;
    if (i < N_EDGES / 2) {
        int2 s = ((const int2*)src)[i];
        int2 d = ((const int2*)dst)[i];
        int p0 = atomicAdd(&g_count[d.x], 1);
        int p1 = atomicAdd(&g_count[d.y], 1);
        if (p0 < PAD) g_nbr[(size_t)d.x * PAD + p0] = s.x;
        if (p1 < PAD) g_nbr[(size_t)d.y * PAD + p1] = s.y;
    }
    if (i < N_NODES * D / 4) {
        float4 v = ((const float4*)x)[i];
        uint2 u;
        u.x = h2u(__floats2half2_rn(v.x, v.y));
        u.y = h2u(__floats2half2_rn(v.z, v.w));
        ((uint2*)g_x16)[i] = u;
    }
    if (i < 2 * 8192) {
        int L = i >> 13;
        int idx = i & 8191;
        int k = idx >> 6;
        int n = idx & 63;
        const float* Wl = L ? Wl2 : Wl1;
        const float* Wr = L ? Wr2 : Wr1;
        float w = (k < 64) ? Wl[idx] : Wr[idx - 4096];
        __half h, l;
        h_split(w, h, l);
        g_whi[L][n * 128 + k] = h;
        g_wlo[L][n * 128 + k] = l;
    }
}

// ---------------------------------------------------------------------------
// Fused tile kernel: fp16 gather (padded adjacency) -> 2-pass mma.sync f16
//   A = [mean_agg | feat]  (128 x 128 halves, fp16)
//   B = Wcat^T  (64 x 128), fp16 hi/lo, precomputed
//   Y = relu(A @ B^T + bl)
// FINAL=false: Y -> g_h16 ; FINAL=true: out = Y @ Wfc + bfc, clears g_count
// Block = 512 threads = 16 warps; warp w: m-band (w>>1)*16, n-half (w&1)*32.
// ---------------------------------------------------------------------------
template <bool FINAL>
__global__ void __launch_bounds__(512, 2) fused_tile_kernel(
    const __half* __restrict__ Whi,
    const __half* __restrict__ Wlo,
    const float* __restrict__ bl,
    const float* __restrict__ Wfc,
    const float* __restrict__ bfc,
    float* __restrict__ outp) {
    extern __shared__ char smem[];
    float* sBias = (float*)(smem + SM_BIAS);
    float* sFc = (float*)(smem + SM_FC);
    float* sOut = (float*)(smem + SM_OUT);

    const int tid = threadIdx.x;
    const int wid = tid >> 5;
    const int lane = tid & 31;
    const int nbase = blockIdx.x * TILE_M;
    const __half* gsrc = FINAL ? g_h16 : g_x16;

    if (tid < D) {
        sBias[tid] = bl[tid];
        if (FINAL) sFc[tid] = Wfc[tid];
    }
    if (FINAL && tid < TILE_M) sOut[tid] = 0.f;

    // ---- Stage weights: coalesced uint4 loads of precomputed hi/lo tiles ----
#pragma unroll
    for (int it = 0; it < 2; it++) {
        int idx = tid + 512 * it;          // 0..1023
        int n = idx >> 4;
        int q = idx & 15;
        uint4 vh = ((const uint4*)Whi)[idx];
        uint4 vl = ((const uint4*)Wlo)[idx];
        *(uint4*)(smem + SM_BHI + ((size_t)n * B_STRIDE + q * 8) * 2) = vh;
        *(uint4*)(smem + SM_BLO + ((size_t)n * B_STRIDE + q * 8) * 2) = vl;
    }

    // ---- Stage X half (cols 64..127 of A), raw fp16 copy ----
#pragma unroll
    for (int r = 0; r < 8; r++) {
        int m = wid + 16 * r;
        int n = nbase + m;
        uint32_t pv = 0;
        if (n < N_NODES) {
            pv = ((const uint32_t*)(gsrc + (size_t)n * D))[lane];
        }
        *(uint32_t*)(smem + SM_A + ((size_t)m * A_STRIDE + 64 + lane * 2) * 2) = pv;
    }

    // ---- Gather (cols 0..63 of A): half-warp per row, padded adjacency ----
    // 16 lanes x uint2 (4 halves) = 128B coalesced per neighbor row.
    {
        const int hw = lane >> 4;    // half-warp 0/1
        const int c = lane & 15;     // column quad (4 halves = 8B)
#pragma unroll
        for (int i = 0; i < 4; i++) {
            const int m = (wid * 2 + hw) + 32 * i;
            const int n = nbase + m;
            float a0 = 0.f, a1 = 0.f, a2 = 0.f, a3 = 0.f;
            float b0 = 0.f, b1 = 0.f, b2 = 0.f, b3 = 0.f;
            float inv = 0.f;
            if (n < N_NODES) {
                const int cnt = g_count[n];
                const int* nb = g_nbr + (size_t)n * PAD;
                inv = cnt > 0 ? 1.0f / (float)cnt : 0.f;
                int j = 0;
                for (; j + 1 < cnt; j += 2) {
                    const int s0 = nb[j];
                    const int s1 = nb[j + 1];
                    uint2 u0 = ((const uint2*)(gsrc + (size_t)s0 * D))[c];
                    uint2 u1 = ((const uint2*)(gsrc + (size_t)s1 * D))[c];
                    float2 f0 = __half22float2(*(const __half2*)&u0.x);
                    float2 f1 = __half22float2(*(const __half2*)&u0.y);
                    float2 f2 = __half22float2(*(const __half2*)&u1.x);
                    float2 f3 = __half22float2(*(const __half2*)&u1.y);
                    a0 += f0.x; a1 += f0.y; a2 += f1.x; a3 += f1.y;
                    b0 += f2.x; b1 += f2.y; b2 += f3.x; b3 += f3.y;
                }
                if (j < cnt) {
                    const int s0 = nb[j];
                    uint2 u0 = ((const uint2*)(gsrc + (size_t)s0 * D))[c];
                    float2 f0 = __half22float2(*(const __half2*)&u0.x);
                    float2 f1 = __half22float2(*(const __half2*)&u0.y);
                    a0 += f0.x; a1 += f0.y; a2 += f1.x; a3 += f1.y;
                }
            }
            a0 += b0; a1 += b1; a2 += b2; a3 += b3;
            uint2 pk;
            pk.x = h2u(__floats2half2_rn(a0 * inv, a1 * inv));
            pk.y = h2u(__floats2half2_rn(a2 * inv, a3 * inv));
            *(uint2*)(smem + SM_A + ((size_t)m * A_STRIDE + 4 * c) * 2) = pk;
        }
    }

    __syncthreads();

    // Layer 2 consumed g_count — clear it for the next harness call.
    if (FINAL && tid < TILE_M) {
        int n = nbase + tid;
        if (n < N_NODES) g_count[n] = 0;
    }

    // ---- Dense: Y = A @ B^T via mma.sync f16, 2-pass (B hi/lo) ----
    const int g = lane >> 2;
    const int t = lane & 3;
    const int mb = wid >> 1;      // m-band 0..7
    const int nh = wid & 1;       // n-half 0..1

    float acc[4][4];
#pragma unroll
    for (int s = 0; s < 4; s++)
#pragma unroll
        for (int q = 0; q < 4; q++) acc[s][q] = 0.f;

    const char* pA = smem + SM_A;
    const char* pBhi = smem + SM_BHI;
    const char* pBlo = smem + SM_BLO;
    const size_t rowA = (size_t)(mb * 16 + g) * A_STRIDE;
    const size_t rowA8 = rowA + (size_t)8 * A_STRIDE;

#pragma unroll
    for (int ks = 0; ks < 8; ks++) {
        const int k0 = ks * 16;
        uint32_t a[4];
        a[0] = *(const uint32_t*)(pA + (rowA + k0 + 2 * t) * 2);
        a[1] = *(const uint32_t*)(pA + (rowA8 + k0 + 2 * t) * 2);
        a[2] = *(const uint32_t*)(pA + (rowA + k0 + 8 + 2 * t) * 2);
        a[3] = *(const uint32_t*)(pA + (rowA8 + k0 + 8 + 2 * t) * 2);
#pragma unroll
        for (int sub = 0; sub < 4; sub++) {
            const int n = nh * 32 + sub * 8 + g;
            const size_t rowB = (size_t)n * B_STRIDE;
            uint32_t bh0 = *(const uint32_t*)(pBhi + (rowB + k0 + 2 * t) * 2);
            uint32_t bh1 = *(const uint32_t*)(pBhi + (rowB + k0 + 8 + 2 * t) * 2);
            uint32_t bl0 = *(const uint32_t*)(pBlo + (rowB + k0 + 2 * t) * 2);
            uint32_t bl1 = *(const uint32_t*)(pBlo + (rowB + k0 + 8 + 2 * t) * 2);
            mma_f16(acc[sub], a, bh0, bh1);
            mma_f16(acc[sub], a, bl0, bl1);
        }
    }

    // ---- Epilogue ----
    const int m0 = mb * 16 + g;
    const int m1 = m0 + 8;
    if (!FINAL) {
#pragma unroll
        for (int sub = 0; sub < 4; sub++) {
            const int col = nh * 32 + sub * 8 + 2 * t;
            const float b0 = sBias[col];
            const float b1 = sBias[col + 1];
            const int n0 = nbase + m0;
            const int n1 = nbase + m1;
            if (n0 < N_NODES) {
                float v0 = fmaxf(acc[sub][0] + b0, 0.f);
                float v1 = fmaxf(acc[sub][1] + b1, 0.f);
                *(uint32_t*)((char*)g_h16 + ((size_t)n0 * D + col) * 2) =
                    h2u(__floats2half2_rn(v0, v1));
            }
            if (n1 < N_NODES) {
                float v0 = fmaxf(acc[sub][2] + b0, 0.f);
                float v1 = fmaxf(acc[sub][3] + b1, 0.f);
                *(uint32_t*)((char*)g_h16 + ((size_t)n1 * D + col) * 2) =
                    h2u(__floats2half2_rn(v0, v1));
            }
        }
    } else {
        float p0 = 0.f, p1 = 0.f;
#pragma unroll
        for (int sub = 0; sub < 4; sub++) {
            const int col = nh * 32 + sub * 8 + 2 * t;
            const float b0 = sBias[col];
            const float b1 = sBias[col + 1];
            const float f0 = sFc[col];
            const float f1 = sFc[col + 1];
            p0 += fmaxf(acc[sub][0] + b0, 0.f) * f0 + fmaxf(acc[sub][1] + b1, 0.f) * f1;
            p1 += fmaxf(acc[sub][2] + b0, 0.f) * f0 + fmaxf(acc[sub][3] + b1, 0.f) * f1;
        }
        p0 += __shfl_xor_sync(0xFFFFFFFFu, p0, 1);
        p0 += __shfl_xor_sync(0xFFFFFFFFu, p0, 2);
        p1 += __shfl_xor_sync(0xFFFFFFFFu, p1, 1);
        p1 += __shfl_xor_sync(0xFFFFFFFFu, p1, 2);
        if (t == 0) {
            atomicAdd(sOut + m0, p0);
            atomicAdd(sOut + m1, p1);
        }
        __syncthreads();
        if (tid < TILE_M) {
            int n = nbase + tid;
            if (n < N_NODES) outp[n] = sOut[tid] + bfc[0];
        }
    }
}

// ---------------------------------------------------------------------------
// Launch
// ---------------------------------------------------------------------------
extern "C" void kernel_launch(void* const* d_in, const int* in_sizes, int n_in,
                              void* d_out, int out_size) {
    const float* x = (const float*)d_in[0];
    const int* ei = (const int*)d_in[1];
    const float* Wl1 = (const float*)d_in[2];
    const float* bl1 = (const float*)d_in[3];
    const float* Wr1 = (const float*)d_in[4];
    const float* Wl2 = (const float*)d_in[5];
    const float* bl2 = (const float*)d_in[6];
    const float* Wr2 = (const float*)d_in[7];
    const float* Wfc = (const float*)d_in[8];
    const float* bfc = (const float*)d_in[9];
    float* out = (float*)d_out;

    const int* src = ei;
    const int* dst = ei + N_EDGES;

    const int bblk = (N_NODES * D / 4 + 255) / 256;   // 6250: covers all 3 tasks

    cudaFuncSetAttribute(fused_tile_kernel<false>,
                         cudaFuncAttributeMaxDynamicSharedMemorySize, SMEM_TOTAL);
    cudaFuncSetAttribute(fused_tile_kernel<true>,
                         cudaFuncAttributeMaxDynamicSharedMemorySize, SMEM_TOTAL);

    __half* whi_dev = nullptr;
    __half* wlo_dev = nullptr;
    cudaGetSymbolAddress((void**)&whi_dev, g_whi);
    cudaGetSymbolAddress((void**)&wlo_dev, g_wlo);

    // One-pass build (g_count is zero on entry; layer-2 kernel re-zeroes)
    build_kernel<<<bblk, 256>>>(src, dst, x, Wl1, Wr1, Wl2, Wr2);

    // Layer 1 (fused fp16 gather + 2-pass mma.sync dense)
    fused_tile_kernel<false><<<NODE_BLOCKS, 512, SMEM_TOTAL>>>(
        whi_dev, wlo_dev, bl1, nullptr, nullptr, nullptr);

    // Layer 2 + head
    fused_tile_kernel<true><<<NODE_BLOCKS, 512, SMEM_TOTAL>>>(
        whi_dev + 64 * 128, wlo_dev + 64 * 128, bl2, Wfc, bfc, out);
}